// round 13
// baseline (speedup 1.0000x reference)
#include <cuda_runtime.h>
#include <cuda_bf16.h>

// Single-launch top-10% mask via max-based band + in-block refinement.
// Grid 2048 x 512 (regs capped by __launch_bounds__(512,3)).
// P0: blocks 0..127 (64/matrix) compute sample max over 1/16 prefix ->
//     band [Tlo,Thi) = 0.9*max*(1 -+ 1e-3) (order-statistic theory: ~12
//     sigma margins; ~30K candidates). Other blocks spin on g_ready.
// P1: ALL blocks: fused pass = provisional mask (k>=Tlo -> 1), count
//     k>=Thi, compact band candidates (smem-staged).
// P2: per-matrix arrive barrier (phase-counting, replay-safe); blocks 0/1
//     each refine their matrix's candidates ENTIRELY IN-BLOCK (radix
//     narrowing over <=30K keys, exact threshold T + residual z, zero
//     k<T, stable argsort tie fixup), then reset state for next replay.
// Any band infeasibility is DETECTED -> exact single-block rescue
// (correctness unconditional regardless of data distribution).

#define TPB      512
#define NBLK     2048
#define NBM      (NBLK / 2)
#define SBLK     128
#define NST      2048
#define CAND_CAP (1u << 19)
#define BLK_CAP  512
#define EPS      1.0e-3f

__device__ unsigned g_maxk[2];
__device__ unsigned g_sdone[2];
__device__ unsigned g_ready[2];
__device__ unsigned g_Tlo[2], g_Thi[2];
__device__ unsigned g_cand_idx[2][CAND_CAP];
__device__ unsigned g_cand_key[2][CAND_CAP];
__device__ unsigned g_cand_cnt[2];
__device__ unsigned g_hiCnt[2];
__device__ unsigned g_fail[2];
__device__ unsigned g_acount[2];
__device__ unsigned g_aphase[2];   // monotone across replays; never reset

__device__ __forceinline__ unsigned abskey(float v) {
    return __float_as_uint(v) & 0x7FFFFFFFu;
}

// Exact single-block rescue over the full matrix (only on detected failure).
__device__ void rescue_block(const float* __restrict__ in, float* __restrict__ dst,
                             int n, unsigned target_top, unsigned* sh) {
    __shared__ unsigned r_lo, r_span, r_rank;
    const int t = threadIdx.x;
    if (t == 0) { r_lo = 0; r_span = 1u << 30; r_rank = (unsigned)n - target_top; }
    __syncthreads();
    while (r_span > 1) {
        unsigned lo = r_lo, span = r_span;
        unsigned s = (span > (unsigned)NST) ? (unsigned)(32 - __clz(span - 1) - 11) : 0u;
        for (int i = t; i < NST; i += TPB) sh[i] = 0;
        __syncthreads();
        for (int i = t; i < n; i += TPB) {
            unsigned d = abskey(in[i]) - lo;
            if (d < span) atomicAdd(&sh[d >> s], 1u);
        }
        __syncthreads();
        if (t == 0) {
            unsigned rank = r_rank, run = 0;
            for (int i = 0; i < NST; i++) {
                unsigned cc = sh[i];
                if (rank < run + cc) { r_lo = lo + ((unsigned)i << s); r_span = 1u << s; r_rank = rank - run; break; }
                run += cc;
            }
        }
        __syncthreads();
    }
    unsigned T = r_lo, z = r_rank;
    for (int i = t; i < n; i += TPB) {
        unsigned k = abskey(in[i]);
        if (k != T) dst[i] = (k > T) ? 1.0f : 0.0f;
    }
    __syncthreads();
    if (t == 0) {
        unsigned seen = 0;
        for (int i = 0; i < n; i++)
            if (abskey(in[i]) == T) { dst[i] = (seen < z) ? 0.0f : 1.0f; seen++; }
    }
    __syncthreads();
}

__global__ void __launch_bounds__(TPB, 3)
mask_kernel(const float4* __restrict__ A, const float4* __restrict__ B,
            float4* __restrict__ out, int n4, int chunk, unsigned target_top) {
    __shared__ unsigned sh[NST];          // hist / rescue scratch
    __shared__ unsigned tot[TPB];         // scan scratch
    __shared__ unsigned sidx[BLK_CAP];
    __shared__ unsigned skey[BLK_CAP];
    __shared__ unsigned sv0, sv1, sv2, sflag;
    const int m = blockIdx.x & 1;
    const int bl = blockIdx.x >> 1;
    const int t = threadIdx.x;
    const int n = n4 * 4;
    const float4* __restrict__ in4 = m ? B : A;
    float4* __restrict__ dst4 = out + (size_t)m * (size_t)n4;
    float* __restrict__ dst1 = (float*)dst4;

    // ---- P0: sample max over 1/16 prefix (blocks 0..127; 64 per matrix) ----
    if (blockIdx.x < SBLK) {
        const int sbl = blockIdx.x >> 1;              // 0..63
        const int beg = sbl * chunk, end = beg + chunk;
        unsigned mk = 0;
        for (int i = beg + t; i < end; i += TPB) {
            float4 v = in4[i];
            mk = max(mk, abskey(v.x));
            mk = max(mk, abskey(v.y));
            mk = max(mk, abskey(v.z));
            mk = max(mk, abskey(v.w));
        }
        for (int off = 16; off > 0; off >>= 1)
            mk = max(mk, __shfl_xor_sync(0xFFFFFFFFu, mk, off));
        if ((t & 31) == 0) tot[t >> 5] = mk;
        __syncthreads();
        if (t == 0) {
            unsigned bm = 0;
            for (int w = 0; w < TPB / 32; w++) bm = max(bm, tot[w]);
            atomicMax(&g_maxk[m], bm);
            __threadfence();
            sflag = (atomicAdd(&g_sdone[m], 1u) == (unsigned)(SBLK / 2 - 1)) ? 1u : 0u;
        }
        __syncthreads();
        if (sflag && t == 0) {
            __threadfence();
            float mv = __uint_as_float(atomicAdd(&g_maxk[m], 0u));
            float c = 0.9f * mv;
            unsigned tlo = abskey(c * (1.0f - EPS));
            unsigned thi = abskey(c * (1.0f + EPS)) + 1u;
            if (thi <= tlo) thi = tlo + 1u;
            g_Tlo[m] = tlo;
            g_Thi[m] = thi;
            __threadfence();
            atomicExch(&g_ready[m], 1u);
        }
    }

    // ---- wait for band ----
    if (t == 0) {
        while (*(volatile unsigned*)&g_ready[m] == 0u) __nanosleep(64);
        sv0 = 0; sv2 = 0;
    }
    __syncthreads();
    __threadfence();
    const unsigned Tlo = *(volatile unsigned*)&g_Tlo[m];
    const unsigned Thi = *(volatile unsigned*)&g_Thi[m];

    // ---- P1: fused pass: mask write + hi count + band compaction ----
    {
        unsigned hi = 0;
        const int stride = NBM * TPB;
        int i0 = bl * TPB + t;
        for (int i = i0; i < n4; i += 2 * stride) {
            int i2 = i + stride;
            float4 v0 = in4[i];
            float4 v1 = (i2 < n4) ? in4[i2] : make_float4(0.f, 0.f, 0.f, 0.f);
            float4 r0, r1;
            unsigned b0 = ((unsigned)i) << 2;
            unsigned b1 = ((unsigned)i2) << 2;
            unsigned k;

            k = abskey(v0.x); r0.x = (k >= Tlo) ? 1.0f : 0.0f; hi += (k >= Thi);
            if (k >= Tlo && k < Thi) { unsigned p = atomicAdd(&sv0, 1u); if (p < BLK_CAP) { sidx[p] = b0;     skey[p] = k; } }
            k = abskey(v0.y); r0.y = (k >= Tlo) ? 1.0f : 0.0f; hi += (k >= Thi);
            if (k >= Tlo && k < Thi) { unsigned p = atomicAdd(&sv0, 1u); if (p < BLK_CAP) { sidx[p] = b0 + 1; skey[p] = k; } }
            k = abskey(v0.z); r0.z = (k >= Tlo) ? 1.0f : 0.0f; hi += (k >= Thi);
            if (k >= Tlo && k < Thi) { unsigned p = atomicAdd(&sv0, 1u); if (p < BLK_CAP) { sidx[p] = b0 + 2; skey[p] = k; } }
            k = abskey(v0.w); r0.w = (k >= Tlo) ? 1.0f : 0.0f; hi += (k >= Thi);
            if (k >= Tlo && k < Thi) { unsigned p = atomicAdd(&sv0, 1u); if (p < BLK_CAP) { sidx[p] = b0 + 3; skey[p] = k; } }
            dst4[i] = r0;

            if (i2 < n4) {
                k = abskey(v1.x); r1.x = (k >= Tlo) ? 1.0f : 0.0f; hi += (k >= Thi);
                if (k >= Tlo && k < Thi) { unsigned p = atomicAdd(&sv0, 1u); if (p < BLK_CAP) { sidx[p] = b1;     skey[p] = k; } }
                k = abskey(v1.y); r1.y = (k >= Tlo) ? 1.0f : 0.0f; hi += (k >= Thi);
                if (k >= Tlo && k < Thi) { unsigned p = atomicAdd(&sv0, 1u); if (p < BLK_CAP) { sidx[p] = b1 + 1; skey[p] = k; } }
                k = abskey(v1.z); r1.z = (k >= Tlo) ? 1.0f : 0.0f; hi += (k >= Thi);
                if (k >= Tlo && k < Thi) { unsigned p = atomicAdd(&sv0, 1u); if (p < BLK_CAP) { sidx[p] = b1 + 2; skey[p] = k; } }
                k = abskey(v1.w); r1.w = (k >= Tlo) ? 1.0f : 0.0f; hi += (k >= Thi);
                if (k >= Tlo && k < Thi) { unsigned p = atomicAdd(&sv0, 1u); if (p < BLK_CAP) { sidx[p] = b1 + 3; skey[p] = k; } }
                dst4[i2] = r1;
            }
        }
        for (int off = 16; off > 0; off >>= 1) hi += __shfl_down_sync(0xFFFFFFFFu, hi, off);
        if ((t & 31) == 0 && hi) atomicAdd(&sv2, hi);
        __syncthreads();
        if (t == 0) {
            if (sv2) atomicAdd(&g_hiCnt[m], sv2);
            unsigned c = sv0;
            if (c > BLK_CAP) { atomicExch(&g_fail[m], 1u); c = BLK_CAP; }
            sv0 = c;
            sv1 = atomicAdd(&g_cand_cnt[m], c);
        }
        __syncthreads();
        unsigned c = sv0, bpos = sv1;
        for (unsigned p = t; p < c; p += TPB) {
            unsigned gp = bpos + p;
            if (gp < CAND_CAP) { g_cand_idx[m][gp] = sidx[p]; g_cand_key[m][gp] = skey[p]; }
        }
    }

    // ---- P2: per-matrix arrive barrier (phase-counting, replay-safe) ----
    __threadfence();
    __syncthreads();
    const bool waiter = (bl == 0);
    if (t == 0) {
        unsigned ph = *(volatile unsigned*)&g_aphase[m];
        if (atomicAdd(&g_acount[m], 1u) == (unsigned)NBM - 1u) {
            g_acount[m] = 0;
            __threadfence();
            atomicAdd(&g_aphase[m], 1u);
        } else if (waiter) {
            while (*(volatile unsigned*)&g_aphase[m] == ph) __nanosleep(64);
        }
        __threadfence();
    }
    __syncthreads();
    if (!waiter) return;

    // ---- refine (one block per matrix, entirely in-block) ----
    unsigned cnt_real = *(volatile unsigned*)&g_cand_cnt[m];
    unsigned cnt = min(cnt_real, CAND_CAP);
    unsigned hic = *(volatile unsigned*)&g_hiCnt[m];
    bool bad = (*(volatile unsigned*)&g_fail[m] != 0) || (cnt_real > CAND_CAP) ||
               (hic > target_top) || (target_top - hic > cnt);
    bool zerokeep = (!bad) && (hic == target_top);
    unsigned T = Thi, z = 0;
    const unsigned* __restrict__ keys = g_cand_key[m];
    const unsigned* __restrict__ idxs = g_cand_idx[m];

    if (!bad && !zerokeep) {
        unsigned keep = target_top - hic;
        unsigned rank = cnt - keep;            // ascending in-band rank
        unsigned lo = Tlo, span = Thi - Tlo;
        while (span > 1) {
            unsigned s = (span > (unsigned)NST) ? (unsigned)(32 - __clz(span - 1) - 11) : 0u;
            for (int i = t; i < NST; i += TPB) sh[i] = 0;
            __syncthreads();
            for (unsigned c = t; c < cnt; c += TPB) {
                unsigned d = keys[c] - lo;
                if (d < span) atomicAdd(&sh[d >> s], 1u);
            }
            __syncthreads();
            unsigned loc[4], sum = 0;
            #pragma unroll
            for (int i = 0; i < 4; i++) { loc[i] = sh[t * 4 + i]; sum += loc[i]; }
            tot[t] = sum;
            __syncthreads();
            for (int off = 1; off < TPB; off <<= 1) {
                unsigned x = (t >= off) ? tot[t - off] : 0u;
                __syncthreads();
                tot[t] += x;
                __syncthreads();
            }
            unsigned run = tot[t] - sum;
            #pragma unroll
            for (int i = 0; i < 4; i++) {
                if (run <= rank && rank < run + loc[i]) { sv0 = (unsigned)(t * 4 + i); sv1 = rank - run; }
                run += loc[i];
            }
            __syncthreads();
            lo += sv0 << s;
            span = 1u << s;
            rank = sv1;
            __syncthreads();
        }
        T = lo;
        z = rank;
    }

    if (!bad) {
        // final candidate pass: zero k<T, collect equals into sidx
        if (t == 0) sv0 = 0;
        __syncthreads();
        for (unsigned c = t; c < cnt; c += TPB) {
            unsigned k = keys[c];
            if (k < T) {
                dst1[idxs[c]] = 0.0f;
            } else if (k == T) {
                unsigned p = atomicAdd(&sv0, 1u);
                if (p < BLK_CAP) sidx[p] = idxs[c];
            }
        }
        __syncthreads();
        unsigned eq = sv0;
        if (eq > BLK_CAP) {
            bad = true;
        } else {
            // stable argsort tie fixup: zero the first z equals by flat index
            for (unsigned e = t; e < eq; e += TPB) {
                unsigned idx = sidx[e];
                unsigned c2 = 0;
                for (unsigned q = 0; q < eq; q++) c2 += (sidx[q] < idx) ? 1u : 0u;
                if (c2 < z) dst1[idx] = 0.0f;
            }
        }
    }
    if (bad) {
        __syncthreads();
        rescue_block((const float*)in4, dst1, n, target_top, sh);
    }

    // ---- cleanup for next graph replay ----
    __syncthreads();
    if (t == 0) {
        g_maxk[m] = 0;
        g_sdone[m] = 0;
        g_ready[m] = 0;
        g_cand_cnt[m] = 0;
        g_hiCnt[m] = 0;
        g_fail[m] = 0;
    }
}

extern "C" void kernel_launch(void* const* d_in, const int* in_sizes, int n_in,
                              void* d_out, int out_size) {
    const float* A = (const float*)d_in[0];
    const float* B = (const float*)d_in[1];
    float* out = (float*)d_out;

    int n = in_sizes[0];
    int n4 = n / 4;
    unsigned j = (unsigned)((1.0 - 0.1) * (double)n);  // mirrors int((1-k)*n)
    unsigned target_top = (unsigned)n - j;             // # of ones
    int chunk = (n4 / 16) / (SBLK / 2);                // float4s per sample block

    mask_kernel<<<NBLK, TPB>>>((const float4*)A, (const float4*)B, (float4*)out,
                               n4, chunk, target_top);
}